// round 17
// baseline (speedup 1.0000x reference)
#include <cuda_runtime.h>
#include <cuda_bf16.h>
#include <math.h>
#include <stdint.h>

#define N0 4096
#define KP1 3072
#define KP2 1536
#define KP3 768
#define H 200
#define HP 256
#define SKMAX 12

// ---------------- device scratch ----------------
__device__ float g_G[(size_t)N0 * N0];
__device__ __nv_bfloat16 g_adjb[(size_t)N0 * N0];
__device__ __nv_bfloat16 g_A1b[(size_t)KP1 * KP1];
__device__ float g_A2[(size_t)KP2 * KP2];
__device__ float g_A3[(size_t)KP3 * KP3];
__device__ float g_x0[N0 * HP];
__device__ float g_x1[KP1 * HP];
__device__ float g_x2[KP2 * HP];
__device__ float g_x3[KP3 * HP];
__device__ float g_t0[N0 * HP];
__device__ float g_part[(size_t)SKMAX * N0 * HP];
__device__ float g_cur[N0 * HP];
__device__ float g_wpad[5 * HP * HP];
__device__ float g_d0[N0];
__device__ float g_d1[KP1];
__device__ float g_d2[KP2];
__device__ float g_d3[KP3];
__device__ float g_score[N0];
__device__ float g_val[N0];
__device__ int   g_perm0[KP1];
__device__ int   g_perm1[KP2];
__device__ int   g_perm2[KP3];
__device__ int   g_ip0[N0];
__device__ int   g_ip1[KP1];
__device__ int   g_ip2[KP2];

__device__ __forceinline__ void cpa16(uint32_t dst, const void* src) {
    asm volatile("cp.async.cg.shared.global [%0], [%1], 16;\n" :: "r"(dst), "l"(src));
}
__device__ __forceinline__ uint32_t packbf(float x, float y) {
    __nv_bfloat162 h = __floats2bfloat162_rn(x, y);
    return *(uint32_t*)&h;
}
__device__ __forceinline__ uint32_t packbf_res(float x, float y, uint32_t hi) {
    __nv_bfloat162 h = *(__nv_bfloat162*)&hi;
    return packbf(x - __bfloat162float(h.x), y - __bfloat162float(h.y));
}

#define MMA_BF16(c, a, b)                                                         \
    asm volatile(                                                                 \
        "mma.sync.aligned.m16n8k16.row.col.f32.bf16.bf16.f32 "                    \
        "{%0,%1,%2,%3}, {%4,%5,%6,%7}, {%8,%9}, {%0,%1,%2,%3};\n"                 \
        : "+f"((c)[0]), "+f"((c)[1]), "+f"((c)[2]), "+f"((c)[3])                  \
        : "r"((a)[0]), "r"((a)[1]), "r"((a)[2]), "r"((a)[3]),                     \
          "r"((b)[0]), "r"((b)[1]))

// ============ bf16 gathered X·X^T GEMM: C = X[perm]·X[perm]^T, lower triangle ========
__global__ void __launch_bounds__(256) bf16gemm_xxt(
    const __nv_bfloat16* __restrict__ X, float* __restrict__ C, int k, int K,
    const int* __restrict__ perm)
{
    if (blockIdx.x > blockIdx.y) return;

    __shared__ __nv_bfloat16 As[2][128][40];
    __shared__ __nv_bfloat16 Bs[2][128][40];

    int t = threadIdx.x;
    int warp = t >> 5, lane = t & 31;
    int group = lane >> 2, tg = lane & 3;
    int wm = warp >> 2, wn = warp & 3;
    int bm = blockIdx.y * 128, bn = blockIdx.x * 128;

    float c[4][4][4];
#pragma unroll
    for (int mi = 0; mi < 4; mi++)
#pragma unroll
        for (int ni = 0; ni < 4; ni++)
#pragma unroll
            for (int r = 0; r < 4; r++) c[mi][ni][r] = 0.f;

    int lrow = t >> 1;
    int lcol0 = (t & 1) * 16;

    uint32_t aBase = (uint32_t)__cvta_generic_to_shared(&As[0][0][0]);
    uint32_t bBase = (uint32_t)__cvta_generic_to_shared(&Bs[0][0][0]);
    const uint32_t stageB = 128 * 40 * 2;
    uint32_t aDst = aBase + lrow * 80 + lcol0 * 2;
    uint32_t bDst = bBase + lrow * 80 + lcol0 * 2;

    const __nv_bfloat16* aSrcRow = X + (size_t)__ldg(&perm[bm + lrow]) * K + lcol0;
    const __nv_bfloat16* bSrcRow = X + (size_t)__ldg(&perm[bn + lrow]) * K + lcol0;

#define LOAD_STAGE(st, k0)                                        \
    do {                                                          \
        const __nv_bfloat16* ap = aSrcRow + (k0);                 \
        const __nv_bfloat16* bp = bSrcRow + (k0);                 \
        uint32_t ad = aDst + (st) * stageB;                       \
        uint32_t bd = bDst + (st) * stageB;                       \
        cpa16(ad, ap); cpa16(ad + 16, ap + 8);                    \
        cpa16(bd, bp); cpa16(bd + 16, bp + 8);                    \
    } while (0)

    LOAD_STAGE(0, 0);
    asm volatile("cp.async.commit_group;\n");

    int s = 0;
    for (int k0 = 0; k0 < K; k0 += 32) {
        if (k0 + 32 < K) {
            LOAD_STAGE(s ^ 1, k0 + 32);
            asm volatile("cp.async.commit_group;\n");
            asm volatile("cp.async.wait_group 1;\n");
        } else {
            asm volatile("cp.async.wait_group 0;\n");
        }
        __syncthreads();

#pragma unroll
        for (int ks = 0; ks < 2; ks++) {
            int kb = ks * 16;
            uint32_t af[4][4], bf[4][2];
#pragma unroll
            for (int mi = 0; mi < 4; mi++) {
                int rm = wm * 64 + mi * 16 + group;
                af[mi][0] = *(const uint32_t*)&As[s][rm][kb + 2 * tg];
                af[mi][1] = *(const uint32_t*)&As[s][rm + 8][kb + 2 * tg];
                af[mi][2] = *(const uint32_t*)&As[s][rm][kb + 2 * tg + 8];
                af[mi][3] = *(const uint32_t*)&As[s][rm + 8][kb + 2 * tg + 8];
            }
#pragma unroll
            for (int ni = 0; ni < 4; ni++) {
                int cn = wn * 32 + ni * 8 + group;
                bf[ni][0] = *(const uint32_t*)&Bs[s][cn][kb + 2 * tg];
                bf[ni][1] = *(const uint32_t*)&Bs[s][cn][kb + 2 * tg + 8];
            }
#pragma unroll
            for (int mi = 0; mi < 4; mi++)
#pragma unroll
                for (int ni = 0; ni < 4; ni++)
                    MMA_BF16(c[mi][ni], af[mi], bf[ni]);
        }
        __syncthreads();
        s ^= 1;
    }
#undef LOAD_STAGE

#pragma unroll
    for (int mi = 0; mi < 4; mi++) {
        int row0 = bm + wm * 64 + mi * 16 + group;
#pragma unroll
        for (int ni = 0; ni < 4; ni++) {
            int col = bn + wn * 32 + ni * 8 + tg * 2;
            *(float2*)(C + (size_t)row0 * k + col)       = make_float2(c[mi][ni][0], c[mi][ni][1]);
            *(float2*)(C + (size_t)(row0 + 8) * k + col) = make_float2(c[mi][ni][2], c[mi][ni][3]);
        }
    }
}

// ============ prop GEMM: A bf16 (exact), B fp32 hi/lo split, fused dinv scale ========
__global__ void __launch_bounds__(256, 2) bf16gA(
    const __nv_bfloat16* __restrict__ A, const float* __restrict__ B, float* __restrict__ Cpart,
    int M, int N, int K, int lda, int ldb, int ldc, const float* __restrict__ dinv)
{
    extern __shared__ char smc[];
    __nv_bfloat16* asb = (__nv_bfloat16*)smc;
    float* bsf = (float*)(smc + 2 * 128 * 40 * 2);
    float* dvb = bsf + 2 * 32 * 136;

    int t = threadIdx.x;
    int warp = t >> 5, lane = t & 31;
    int group = lane >> 2, tg = lane & 3;
    int wm = warp >> 2, wn = warp & 3;
    int bm = blockIdx.y * 128, bn = blockIdx.x * 128;
    int kChunk = K / gridDim.z;
    int kStart = blockIdx.z * kChunk;
    float* C = Cpart + (size_t)blockIdx.z * M * ldc;

    float c[4][4][4];
#pragma unroll
    for (int mi = 0; mi < 4; mi++)
#pragma unroll
        for (int ni = 0; ni < 4; ni++)
#pragma unroll
            for (int r = 0; r < 4; r++) c[mi][ni][r] = 0.f;

    auto LOADST = [&](int st, int k0) {
        __nv_bfloat16* as = asb + st * (128 * 40);
        float* bs = bsf + st * (32 * 136);
#pragma unroll
        for (int q = 0; q < 2; q++) {
            int idx = t + q * 256;
            int row = idx >> 2, seg = idx & 3;
            uint32_t ad = (uint32_t)__cvta_generic_to_shared(as + row * 40 + seg * 8);
            cpa16(ad, A + (size_t)(bm + row) * lda + kStart + k0 + seg * 8);
        }
#pragma unroll
        for (int q = 0; q < 4; q++) {
            int cc = t + q * 256;
            int r = cc >> 5, nc = cc & 31;
            uint32_t bd = (uint32_t)__cvta_generic_to_shared(bs + r * 136 + nc * 4);
            cpa16(bd, B + (size_t)(kStart + k0 + r) * ldb + bn + nc * 4);
        }
        if (t < 8) {
            uint32_t dd = (uint32_t)__cvta_generic_to_shared(dvb + st * 32 + t * 4);
            cpa16(dd, dinv + kStart + k0 + t * 4);
        }
        asm volatile("cp.async.commit_group;\n");
    };

    LOADST(0, 0);

    int s = 0;
    for (int k0 = 0; k0 < kChunk; k0 += 32) {
        if (k0 + 32 < kChunk) {
            LOADST(s ^ 1, k0 + 32);
            asm volatile("cp.async.wait_group 1;\n");
        } else {
            asm volatile("cp.async.wait_group 0;\n");
        }
        __syncthreads();

        const __nv_bfloat16* as = asb + s * (128 * 40);
        const float* bs = bsf + s * (32 * 136);
        const float* dv = dvb + s * 32;

#pragma unroll
        for (int ks = 0; ks < 2; ks++) {
            int kb = ks * 16;
            uint32_t af[4][4], bh[4][2], bl[4][2];
#pragma unroll
            for (int mi = 0; mi < 4; mi++) {
                int rm = wm * 64 + mi * 16 + group;
                af[mi][0] = *(const uint32_t*)&as[rm * 40 + kb + 2 * tg];
                af[mi][1] = *(const uint32_t*)&as[(rm + 8) * 40 + kb + 2 * tg];
                af[mi][2] = *(const uint32_t*)&as[rm * 40 + kb + 2 * tg + 8];
                af[mi][3] = *(const uint32_t*)&as[(rm + 8) * 40 + kb + 2 * tg + 8];
            }
#pragma unroll
            for (int ni = 0; ni < 4; ni++) {
                int cn = wn * 32 + ni * 8 + group;
                float b0a = bs[(kb + 2 * tg) * 136 + cn]     * dv[kb + 2 * tg];
                float b0b = bs[(kb + 2 * tg + 1) * 136 + cn] * dv[kb + 2 * tg + 1];
                float b1a = bs[(kb + 8 + 2 * tg) * 136 + cn] * dv[kb + 8 + 2 * tg];
                float b1b = bs[(kb + 9 + 2 * tg) * 136 + cn] * dv[kb + 9 + 2 * tg];
                bh[ni][0] = packbf(b0a, b0b);
                bh[ni][1] = packbf(b1a, b1b);
                bl[ni][0] = packbf_res(b0a, b0b, bh[ni][0]);
                bl[ni][1] = packbf_res(b1a, b1b, bh[ni][1]);
            }
#pragma unroll
            for (int mi = 0; mi < 4; mi++)
#pragma unroll
                for (int ni = 0; ni < 4; ni++) {
                    MMA_BF16(c[mi][ni], af[mi], bh[ni]);
                    MMA_BF16(c[mi][ni], af[mi], bl[ni]);
                }
        }
        __syncthreads();
        s ^= 1;
    }

#pragma unroll
    for (int mi = 0; mi < 4; mi++) {
        int row0 = bm + wm * 64 + mi * 16 + group;
#pragma unroll
        for (int ni = 0; ni < 4; ni++) {
            int col = bn + wn * 32 + ni * 8 + tg * 2;
            *(float2*)(C + (size_t)row0 * ldc + col)       = make_float2(c[mi][ni][0], c[mi][ni][1]);
            *(float2*)(C + (size_t)(row0 + 8) * ldc + col) = make_float2(c[mi][ni][2], c[mi][ni][3]);
        }
    }
}

// ============ bf16-split GEMM from fp32 inputs ======================================
template <int ASPLIT, int XXT, int DSCALE, int AMODE>
__global__ void __launch_bounds__(256, (ASPLIT ? 1 : 2)) bf16g(
    const float* __restrict__ A, const float* __restrict__ B, float* __restrict__ Cpart,
    int M, int N, int K, int lda, int ldb, int ldc, const float* __restrict__ dinv,
    const int* __restrict__ pidx, const float* __restrict__ pval)
{
    if (XXT && (int)blockIdx.x > (int)blockIdx.y) return;
    extern __shared__ float smd[];
    const int STAGEF = 9216;
    const int BOFF = 128 * 36;
    float* dvbase = smd + 2 * STAGEF;

    int t = threadIdx.x;
    int warp = t >> 5, lane = t & 31;
    int group = lane >> 2, tg = lane & 3;
    int wm = warp >> 2, wn = warp & 3;
    int bm = blockIdx.y * 128, bn = blockIdx.x * 128;
    int kChunk = K / gridDim.z;
    int kStart = blockIdx.z * kChunk;
    float* C = Cpart + (size_t)blockIdx.z * M * ldc;

    float c[4][4][4];
#pragma unroll
    for (int mi = 0; mi < 4; mi++)
#pragma unroll
        for (int ni = 0; ni < 4; ni++)
#pragma unroll
            for (int r = 0; r < 4; r++) c[mi][ni][r] = 0.f;

    float av0[4], av1[4];
    if (AMODE == 1) {
#pragma unroll
        for (int mi = 0; mi < 4; mi++) {
            int rm = wm * 64 + mi * 16 + group;
            av0[mi] = __ldg(&pval[bm + rm]);
            av1[mi] = __ldg(&pval[bm + rm + 8]);
        }
    }

    auto LOADST = [&](int st, int k0) {
        float* as = smd + st * STAGEF;
        float* bs = as + BOFF;
#pragma unroll
        for (int q = 0; q < 4; q++) {
            int cc = t + q * 256;
            int m = cc >> 3, kc = cc & 7;
            uint32_t ad = (uint32_t)__cvta_generic_to_shared(as + m * 36 + kc * 4);
            size_t srow = (AMODE == 1) ? (size_t)__ldg(&pidx[bm + m]) : (size_t)(bm + m);
            cpa16(ad, A + srow * lda + kStart + k0 + kc * 4);
        }
        if (XXT) {
#pragma unroll
            for (int q = 0; q < 4; q++) {
                int cc = t + q * 256;
                int m = cc >> 3, kc = cc & 7;
                uint32_t bd = (uint32_t)__cvta_generic_to_shared(bs + m * 36 + kc * 4);
                cpa16(bd, B + (size_t)(bn + m) * ldb + kStart + k0 + kc * 4);
            }
        } else {
#pragma unroll
            for (int q = 0; q < 4; q++) {
                int cc = t + q * 256;
                int r = cc >> 5, nc = cc & 31;
                uint32_t bd = (uint32_t)__cvta_generic_to_shared(bs + r * 136 + nc * 4);
                cpa16(bd, B + (size_t)(kStart + k0 + r) * ldb + bn + nc * 4);
            }
            if (DSCALE && t < 8) {
                uint32_t dd = (uint32_t)__cvta_generic_to_shared(dvbase + st * 32 + t * 4);
                cpa16(dd, dinv + kStart + k0 + t * 4);
            }
        }
        asm volatile("cp.async.commit_group;\n");
    };

    LOADST(0, 0);

    int s = 0;
    for (int k0 = 0; k0 < kChunk; k0 += 32) {
        if (k0 + 32 < kChunk) {
            LOADST(s ^ 1, k0 + 32);
            asm volatile("cp.async.wait_group 1;\n");
        } else {
            asm volatile("cp.async.wait_group 0;\n");
        }
        __syncthreads();

        const float* as = smd + s * STAGEF;
        const float* bs = as + BOFF;
        const float* dv = dvbase + s * 32;

#pragma unroll
        for (int ks = 0; ks < 2; ks++) {
            int kb = ks * 16;
            uint32_t ah[4][4], al[4][4], bh[4][2], bl[4][2];
#pragma unroll
            for (int mi = 0; mi < 4; mi++) {
                int rm = wm * 64 + mi * 16 + group;
                const float* r0 = as + rm * 36 + kb + 2 * tg;
                const float* r1 = as + (rm + 8) * 36 + kb + 2 * tg;
                float x0 = r0[0], x1 = r0[1], x2 = r1[0], x3 = r1[1];
                float x4 = r0[8], x5 = r0[9], x6 = r1[8], x7 = r1[9];
                if (AMODE == 1) {
                    x0 *= av0[mi]; x1 *= av0[mi]; x4 *= av0[mi]; x5 *= av0[mi];
                    x2 *= av1[mi]; x3 *= av1[mi]; x6 *= av1[mi]; x7 *= av1[mi];
                }
                ah[mi][0] = packbf(x0, x1);
                ah[mi][1] = packbf(x2, x3);
                ah[mi][2] = packbf(x4, x5);
                ah[mi][3] = packbf(x6, x7);
                if (ASPLIT) {
                    al[mi][0] = packbf_res(x0, x1, ah[mi][0]);
                    al[mi][1] = packbf_res(x2, x3, ah[mi][1]);
                    al[mi][2] = packbf_res(x4, x5, ah[mi][2]);
                    al[mi][3] = packbf_res(x6, x7, ah[mi][3]);
                }
            }
#pragma unroll
            for (int ni = 0; ni < 4; ni++) {
                int cn = wn * 32 + ni * 8 + group;
                float b0a, b0b, b1a, b1b;
                if (XXT) {
                    const float* rb = bs + cn * 36 + kb + 2 * tg;
                    b0a = rb[0]; b0b = rb[1]; b1a = rb[8]; b1b = rb[9];
                } else {
                    b0a = bs[(kb + 2 * tg) * 136 + cn];
                    b0b = bs[(kb + 2 * tg + 1) * 136 + cn];
                    b1a = bs[(kb + 8 + 2 * tg) * 136 + cn];
                    b1b = bs[(kb + 9 + 2 * tg) * 136 + cn];
                    if (DSCALE) {
                        b0a *= dv[kb + 2 * tg];
                        b0b *= dv[kb + 2 * tg + 1];
                        b1a *= dv[kb + 8 + 2 * tg];
                        b1b *= dv[kb + 9 + 2 * tg];
                    }
                }
                bh[ni][0] = packbf(b0a, b0b);
                bh[ni][1] = packbf(b1a, b1b);
                bl[ni][0] = packbf_res(b0a, b0b, bh[ni][0]);
                bl[ni][1] = packbf_res(b1a, b1b, bh[ni][1]);
            }
#pragma unroll
            for (int mi = 0; mi < 4; mi++)
#pragma unroll
                for (int ni = 0; ni < 4; ni++) {
                    MMA_BF16(c[mi][ni], ah[mi], bh[ni]);
                    MMA_BF16(c[mi][ni], ah[mi], bl[ni]);
                    if (ASPLIT) MMA_BF16(c[mi][ni], al[mi], bh[ni]);
                }
        }
        __syncthreads();
        s ^= 1;
    }

#pragma unroll
    for (int mi = 0; mi < 4; mi++) {
        int row0 = bm + wm * 64 + mi * 16 + group;
#pragma unroll
        for (int ni = 0; ni < 4; ni++) {
            int col = bn + wn * 32 + ni * 8 + tg * 2;
            *(float2*)(C + (size_t)row0 * ldc + col)       = make_float2(c[mi][ni][0], c[mi][ni][1]);
            *(float2*)(C + (size_t)(row0 + 8) * ldc + col) = make_float2(c[mi][ni][2], c[mi][ni][3]);
        }
    }
}

// ---------------- generic SGEMM (small K paths), zero-pads cols [N, npad) ------------
__global__ void __launch_bounds__(256) gemm64(
    const float* __restrict__ A, const float* __restrict__ B, float* __restrict__ C,
    int M, int N, int K, int lda, int ldb, int ldc, int npad)
{
    __shared__ float As[16][65];
    __shared__ float Bs[16][64];
    int tid = threadIdx.x, tx = tid & 15, ty = tid >> 4;
    int bm = blockIdx.y * 64, bn = blockIdx.x * 64;
    float acc[4][4];
#pragma unroll
    for (int i = 0; i < 4; i++)
#pragma unroll
        for (int j = 0; j < 4; j++) acc[i][j] = 0.f;

    for (int k0 = 0; k0 < K; k0 += 16) {
        for (int t = tid; t < 64 * 16; t += 256) {
            int r = t >> 4, c = t & 15;
            int gr = bm + r, gc = k0 + c;
            As[c][r] = (gr < M && gc < K) ? A[(size_t)gr * lda + gc] : 0.f;
        }
        for (int t = tid; t < 16 * 64; t += 256) {
            int r = t >> 6, c = t & 63;
            int gr = k0 + r, gc = bn + c;
            Bs[r][c] = (gr < K && gc < N) ? B[(size_t)gr * ldb + gc] : 0.f;
        }
        __syncthreads();
#pragma unroll
        for (int kk = 0; kk < 16; kk++) {
            float a[4], b[4];
#pragma unroll
            for (int i = 0; i < 4; i++) a[i] = As[kk][ty * 4 + i];
#pragma unroll
            for (int j = 0; j < 4; j++) b[j] = Bs[kk][tx * 4 + j];
#pragma unroll
            for (int i = 0; i < 4; i++)
#pragma unroll
                for (int j = 0; j < 4; j++) acc[i][j] += a[i] * b[j];
        }
        __syncthreads();
    }
#pragma unroll
    for (int i = 0; i < 4; i++)
#pragma unroll
        for (int j = 0; j < 4; j++) {
            int gr = bm + ty * 4 + i, gc = bn + tx * 4 + j;
            if (gr < M && gc < npad) C[(size_t)gr * ldc + gc] = (gc < N) ? acc[i][j] : 0.f;
        }
}

// ---------------- small helper kernels ----------------
__global__ void pad_w5(const float* __restrict__ a, const float* __restrict__ b,
                       const float* __restrict__ c, const float* __restrict__ d,
                       const float* __restrict__ e, float* __restrict__ out)
{
    int idx = blockIdx.x * 256 + threadIdx.x;
    if (idx >= 5 * HP * HP) return;
    int w = idx / (HP * HP), r = idx - w * (HP * HP);
    int i = r >> 8, j = r & 255;
    const float* W = (w == 0) ? a : (w == 1) ? b : (w == 2) ? c : (w == 3) ? d : e;
    out[idx] = (i < H && j < H) ? W[i * H + j] : 0.f;
}

__global__ void f32tobf16(const float* __restrict__ in, __nv_bfloat16* __restrict__ out,
                          size_t n4)
{
    size_t i = (size_t)blockIdx.x * 256 + threadIdx.x;
    if (i >= n4) return;
    float4 v = *(const float4*)(in + i * 4);
    __nv_bfloat162 a = __floats2bfloat162_rn(v.x, v.y);
    __nv_bfloat162 b = __floats2bfloat162_rn(v.z, v.w);
    *(__nv_bfloat162*)(out + i * 4)     = a;
    *(__nv_bfloat162*)(out + i * 4 + 2) = b;
}

__global__ void rowgather_f32(const float* __restrict__ A, int n,
                              const int* __restrict__ perm,
                              float* __restrict__ out, int krows)
{
    size_t idx = (size_t)blockIdx.x * 256 + threadIdx.x;
    size_t n4 = (size_t)n / 4;
    if (idx >= (size_t)krows * n4) return;
    int i = (int)(idx / n4);
    int j4 = (int)(idx - (size_t)i * n4);
    float4 v = *(const float4*)(A + (size_t)perm[i] * n + j4 * 4);
    *(float4*)(out + (size_t)i * n + j4 * 4) = v;
}

__global__ void rowsum_dinv(const float* __restrict__ A, float* __restrict__ dinv, int n)
{
    int row = blockIdx.x;
    const float* Ar = A + (size_t)row * n;
    float s = 0.f;
    for (int j = threadIdx.x; j < n; j += 256) s += Ar[j];
    for (int o = 16; o > 0; o >>= 1) s += __shfl_down_sync(0xffffffffu, s, o);
    __shared__ float red[8];
    int w = threadIdx.x >> 5, l = threadIdx.x & 31;
    if (l == 0) red[w] = s;
    __syncthreads();
    if (threadIdx.x == 0) {
        float t = 0.f;
        for (int i = 0; i < 8; i++) t += red[i];
        dinv[row] = 1.0f / sqrtf(t + 2.0f);
    }
}

__global__ void rowsum_dinv_bf(const __nv_bfloat16* __restrict__ A, float* __restrict__ dinv, int n)
{
    int row = blockIdx.x;
    const __nv_bfloat16* Ar = A + (size_t)row * n;
    float s = 0.f;
    for (int j = threadIdx.x * 2; j < n; j += 512) {
        __nv_bfloat162 v = *(const __nv_bfloat162*)(Ar + j);
        s += __bfloat162float(v.x) + __bfloat162float(v.y);
    }
    for (int o = 16; o > 0; o >>= 1) s += __shfl_down_sync(0xffffffffu, s, o);
    __shared__ float red[8];
    int w = threadIdx.x >> 5, l = threadIdx.x & 31;
    if (l == 0) red[w] = s;
    __syncthreads();
    if (threadIdx.x == 0) {
        float t = 0.f;
        for (int i = 0; i < 8; i++) t += red[i];
        dinv[row] = 1.0f / sqrtf(t + 2.0f);
    }
}

// plain finish (no score): out = dinv*(az + 2*(dinv*Z)) + b, relu
__global__ void gcn_finish_sk(const float* __restrict__ part, const float* __restrict__ Z,
                              const float* __restrict__ dinv, const float* __restrict__ b,
                              float* __restrict__ out, int n, int relu, int S)
{
    int idx = blockIdx.x * 256 + threadIdx.x;
    if (idx >= n * HP) return;
    int r = idx >> 8, c = idx & 255;
    float v = 0.f;
    if (c < H) {
        float az = 0.f;
        size_t stride = (size_t)n * HP;
        for (int s = 0; s < S; s++) az += part[s * stride + idx];
        float dr = dinv[r];
        v = dr * (az + 2.f * (dr * Z[idx])) + b[c];
        if (relu) v = fmaxf(v, 0.f);
    }
    out[idx] = v;
}

// fused finish + score: one warp per row; X written AND score computed (relu always on)
__global__ void gcn_finish_score(const float* __restrict__ part, const float* __restrict__ Z,
                                 const float* __restrict__ dinv, const float* __restrict__ b,
                                 const float* __restrict__ p,
                                 float* __restrict__ out, float* __restrict__ score,
                                 int n, int S)
{
    int row = blockIdx.x * 8 + (threadIdx.x >> 5);
    int lane = threadIdx.x & 31;
    if (row >= n) return;
    float dr = dinv[row];
    size_t stride = (size_t)n * HP;
    size_t base = (size_t)row * HP;
    float s = 0.f, pp = 0.f;
    for (int c = lane; c < HP; c += 32) {
        float v = 0.f;
        if (c < H) {
            float az = 0.f;
            size_t idx = base + c;
            for (int s2 = 0; s2 < S; s2++) az += part[s2 * stride + idx];
            v = dr * (az + 2.f * (dr * Z[idx])) + b[c];
            v = fmaxf(v, 0.f);
            float pv = p[c];
            s += v * pv;
            pp += pv * pv;
        }
        out[base + c] = v;
    }
    for (int o = 16; o > 0; o >>= 1) {
        s  += __shfl_down_sync(0xffffffffu, s, o);
        pp += __shfl_down_sync(0xffffffffu, pp, o);
    }
    if (lane == 0) score[row] = tanhf(s / sqrtf(pp));
}

template <int SIZE>
__global__ void topk_kernel(const float* __restrict__ score, int n, int k,
                            int* __restrict__ perm, float* __restrict__ val,
                            int* __restrict__ iperm)
{
    __shared__ unsigned long long key[SIZE];
    int tid = threadIdx.x;
    for (int i = tid; i < SIZE; i += 1024) {
        float s = (i < n) ? score[i] : -INFINITY;
        uint32_t u = __float_as_uint(s);
        u = (u & 0x80000000u) ? ~u : (u | 0x80000000u);
        uint32_t d = ~u;
        key[i] = ((unsigned long long)d << 32) | (uint32_t)i;
        if (i < n) iperm[i] = -1;
    }
    __syncthreads();
    for (int size = 2; size <= SIZE; size <<= 1) {
        for (int stride = size >> 1; stride > 0; stride >>= 1) {
            for (int i = tid; i < SIZE; i += 1024) {
                int j = i ^ stride;
                if (j > i) {
                    unsigned long long a = key[i], b = key[j];
                    bool up = ((i & size) == 0);
                    if (up ? (a > b) : (a < b)) { key[i] = b; key[j] = a; }
                }
            }
            __syncthreads();
        }
    }
    for (int i = tid; i < k; i += 1024) {
        int si = (int)(uint32_t)key[i];
        perm[i] = si;
        val[i] = score[si];
        iperm[si] = i;
    }
}

// level 1: out bf16 (exact small ints); Src = adjB, indexed via perm on both sides
__global__ void pool_A_tri_bf(const float* __restrict__ C, const __nv_bfloat16* __restrict__ Src,
                              int K, const int* __restrict__ perm,
                              __nv_bfloat16* __restrict__ Aout, int k)
{
    int idx = blockIdx.x * 256 + threadIdx.x;
    if (idx >= k * k) return;
    int i = idx / k, j = idx - i * k;
    if (i == j) { Aout[idx] = __float2bfloat16(0.f); return; }
    int hi = i > j ? i : j, lo = i > j ? j : i;
    float g = C[(size_t)hi * k + lo];
    float a = __bfloat162float(Src[(size_t)__ldg(&perm[i]) * K + __ldg(&perm[j])]);
    Aout[idx] = __float2bfloat16(g + 2.f * a);
}

// level 2: out fp32; Src = A1B via perm both sides
__global__ void pool_A_tri(const float* __restrict__ C, const __nv_bfloat16* __restrict__ Src,
                           int K, const int* __restrict__ perm,
                           float* __restrict__ Aout, int k)
{
    int idx = blockIdx.x * 256 + threadIdx.x;
    if (idx >= k * k) return;
    int i = idx / k, j = idx - i * k;
    if (i == j) { Aout[idx] = 0.f; return; }
    int hi = i > j ? i : j, lo = i > j ? j : i;
    float g = C[(size_t)hi * k + lo];
    float a = __bfloat162float(Src[(size_t)__ldg(&perm[i]) * K + __ldg(&perm[j])]);
    Aout[idx] = g + 2.f * a;
}

__global__ void pool_A_tri_f32(const float* __restrict__ C, const float* __restrict__ Rows,
                               int K, const int* __restrict__ perm,
                               float* __restrict__ Aout, int k)
{
    int idx = blockIdx.x * 256 + threadIdx.x;
    if (idx >= k * k) return;
    int i = idx / k, j = idx - i * k;
    if (i == j) { Aout[idx] = 0.f; return; }
    int hi = i > j ? i : j, lo = i > j ? j : i;
    Aout[idx] = C[(size_t)hi * k + lo] + 2.f * Rows[(size_t)i * K + __ldg(&perm[j])];
}

__global__ void fuse_up(const float* __restrict__ Xj, const float* __restrict__ Xn,
                        const int* __restrict__ iperm, float* __restrict__ out, int n)
{
    int idx = blockIdx.x * 256 + threadIdx.x;
    if (idx >= n * HP) return;
    int r = idx >> 8, c = idx & 255;
    int p = iperm[r];
    float v = Xj[idx];
    if (p >= 0) v += Xn[p * HP + c];
    out[idx] = v;
}

// A(bf16, exact binary) @ (diag(dinv)·T0)[n x 2]
__global__ void gemm_n2_bf(const __nv_bfloat16* __restrict__ A, const float* __restrict__ T0,
                           const float* __restrict__ dinv, float* __restrict__ out, int n)
{
    int row = blockIdx.x;
    const __nv_bfloat16* Ar = A + (size_t)row * n;
    float a0 = 0.f, a1 = 0.f;
    for (int j = threadIdx.x; j < n; j += 256) {
        float a = __bfloat162float(Ar[j]);
        float dj = dinv[j];
        a0 += a * (dj * T0[2 * j]);
        a1 += a * (dj * T0[2 * j + 1]);
    }
    for (int o = 16; o > 0; o >>= 1) {
        a0 += __shfl_down_sync(0xffffffffu, a0, o);
        a1 += __shfl_down_sync(0xffffffffu, a1, o);
    }
    __shared__ float r0[8], r1[8];
    int w = threadIdx.x >> 5, l = threadIdx.x & 31;
    if (l == 0) { r0[w] = a0; r1[w] = a1; }
    __syncthreads();
    if (threadIdx.x == 0) {
        float s0 = 0.f, s1 = 0.f;
        for (int i = 0; i < 8; i++) { s0 += r0[i]; s1 += r1[i]; }
        out[2 * row] = s0;
        out[2 * row + 1] = s1;
    }
}

__global__ void final_kernel2(const float* __restrict__ AZ, const float* __restrict__ T0,
                              const float* __restrict__ dinv, const float* __restrict__ b,
                              float* __restrict__ out, int n)
{
    int i = blockIdx.x * 256 + threadIdx.x;
    if (i >= n) return;
    float di = dinv[i];
    float a = di * (AZ[2 * i]     + 2.f * (di * T0[2 * i]))     + b[0];
    float c = di * (AZ[2 * i + 1] + 2.f * (di * T0[2 * i + 1])) + b[1];
    float m = fmaxf(a, c);
    float l = m + logf(expf(a - m) + expf(c - m));
    out[2 * i] = a - l;
    out[2 * i + 1] = c - l;
}

// ---------------- host orchestration ----------------
template <typename T, size_t NN>
static T* symaddr(T (&sym)[NN]) {
    void* p = nullptr;
    cudaGetSymbolAddress(&p, sym);
    return (T*)p;
}

#define SMEM_BF 73984
#define SMEM_BA 55552

extern "C" void kernel_launch(void* const* d_in, const int* in_sizes, int n_in,
                              void* d_out, int out_size)
{
    (void)in_sizes; (void)n_in; (void)out_size;
    const float* x   = (const float*)d_in[0];
    const float* adj = (const float*)d_in[1];
    const float* w0  = (const float*)d_in[2];
    const float* b0  = (const float*)d_in[3];
    const float* w1  = (const float*)d_in[4];
    const float* b1  = (const float*)d_in[5];
    const float* w2  = (const float*)d_in[6];
    const float* b2  = (const float*)d_in[7];
    const float* w3  = (const float*)d_in[8];
    const float* b3  = (const float*)d_in[9];
    const float* p1  = (const float*)d_in[10];
    const float* p2  = (const float*)d_in[11];
    const float* p3  = (const float*)d_in[12];
    const float* u0w = (const float*)d_in[13];
    const float* u0b = (const float*)d_in[14];
    const float* u1w = (const float*)d_in[15];
    const float* u1b = (const float*)d_in[16];
    const float* u2w = (const float*)d_in[17];
    const float* u2b = (const float*)d_in[18];

    static cudaStream_t sA = nullptr;
    static cudaEvent_t evF = nullptr, evA = nullptr, evB = nullptr;
    static bool init_done = false;
    if (!init_done) {
        cudaFuncSetAttribute(bf16gA, cudaFuncAttributeMaxDynamicSharedMemorySize, SMEM_BA);
        cudaFuncSetAttribute(bf16g<1, 0, 1, 0>, cudaFuncAttributeMaxDynamicSharedMemorySize, SMEM_BF);
        cudaFuncSetAttribute(bf16g<1, 0, 0, 0>, cudaFuncAttributeMaxDynamicSharedMemorySize, SMEM_BF);
        cudaFuncSetAttribute(bf16g<1, 0, 0, 1>, cudaFuncAttributeMaxDynamicSharedMemorySize, SMEM_BF);
        cudaFuncSetAttribute(bf16g<1, 1, 0, 0>, cudaFuncAttributeMaxDynamicSharedMemorySize, SMEM_BF);
        cudaStreamCreateWithFlags(&sA, cudaStreamNonBlocking);
        cudaEventCreateWithFlags(&evF, cudaEventDisableTiming);
        cudaEventCreateWithFlags(&evA, cudaEventDisableTiming);
        cudaEventCreateWithFlags(&evB, cudaEventDisableTiming);
        init_done = true;
    }

    float* G    = symaddr(g_G);
    __nv_bfloat16* ADJB = symaddr(g_adjb);
    __nv_bfloat16* A1B  = symaddr(g_A1b);
    float* A2   = symaddr(g_A2);
    float* A3   = symaddr(g_A3);
    float* X0   = symaddr(g_x0);
    float* X1   = symaddr(g_x1);
    float* X2   = symaddr(g_x2);
    float* X3   = symaddr(g_x3);
    float* T0   = symaddr(g_t0);
    float* PART = symaddr(g_part);
    float* CUR  = symaddr(g_cur);
    float* WP   = symaddr(g_wpad);
    float* D0   = symaddr(g_d0);
    float* D1   = symaddr(g_d1);
    float* D2   = symaddr(g_d2);
    float* D3   = symaddr(g_d3);
    float* SC   = symaddr(g_score);
    float* VAL  = symaddr(g_val);
    int*   P0   = symaddr(g_perm0);
    int*   P1   = symaddr(g_perm1);
    int*   P2   = symaddr(g_perm2);
    int*   IP0  = symaddr(g_ip0);
    int*   IP1  = symaddr(g_ip1);
    int*   IP2  = symaddr(g_ip2);

    float* WP_w1  = WP + 0 * HP * HP;
    float* WP_w2  = WP + 1 * HP * HP;
    float* WP_w3  = WP + 2 * HP * HP;
    float* WP_u0w = WP + 3 * HP * HP;
    float* WP_u1w = WP + 4 * HP * HP;

    // ---- fork side stream into capture, then adj->bf16 there ----
    cudaEventRecord(evF, 0);
    cudaStreamWaitEvent(sA, evF, 0);
    {
        size_t n4 = ((size_t)N0 * N0) / 4;
        f32tobf16<<<(unsigned)((n4 + 255) / 256), 256, 0, sA>>>(adj, ADJB, n4);
        cudaEventRecord(evB, sA);
    }
    pad_w5<<<(5 * HP * HP + 255) / 256, 256>>>(w1, w2, w3, u0w, u1w, WP);
    rowsum_dinv<<<N0, 256>>>(adj, D0, N0);

    // ---- gcn0 (finish fused with score for pool 1) ----
    {
        dim3 g1((H + 63) / 64, (N0 + 63) / 64);
        gemm64<<<g1, 256>>>(x, w0, T0, N0, H, 3, 3, H, HP, HP);
        cudaStreamWaitEvent(0, evB, 0);
        dim3 g2(HP / 128, N0 / 128, 4);
        bf16gA<<<g2, 256, SMEM_BA>>>(ADJB, T0, PART, N0, HP, N0, N0, HP, HP, D0);
        gcn_finish_score<<<(N0 + 7) / 8, 256>>>(PART, T0, D0, b0, p1, X0, SC, N0, 4);
    }

    // ==== pool 1 (4096 -> 3072) ====
    topk_kernel<4096><<<1, 1024>>>(SC, N0, KP1, P0, VAL, IP0);
    cudaEventRecord(evF, 0);
    cudaStreamWaitEvent(sA, evF, 0);
    {
        dim3 g(KP1 / 128, KP1 / 128);
        bf16gemm_xxt<<<g, 256, 0, sA>>>(ADJB, G, KP1, N0, P0);
        pool_A_tri_bf<<<(KP1 * KP1 + 255) / 256, 256, 0, sA>>>(G, ADJB, N0, P0, A1B, KP1);
        rowsum_dinv_bf<<<KP1, 256, 0, sA>>>(A1B, D1, KP1);
    }
    cudaEventRecord(evA, sA);
    {
        dim3 gw(HP / 128, KP1 / 128, 1);
        bf16g<1, 0, 0, 1><<<gw, 256, SMEM_BF>>>(X0, WP_w1, T0, KP1, HP, HP, HP, HP, HP,
                                                nullptr, P0, VAL);
    }
    cudaStreamWaitEvent(0, evA, 0);
    {
        dim3 g2(HP / 128, KP1 / 128, 6);
        bf16gA<<<g2, 256, SMEM_BA>>>(A1B, T0, PART, KP1, HP, KP1, KP1, HP, HP, D1);
        gcn_finish_score<<<(KP1 + 7) / 8, 256>>>(PART, T0, D1, b1, p2, X1, SC, KP1, 6);
    }

    // ==== pool 2 (3072 -> 1536) ====
    topk_kernel<4096><<<1, 1024>>>(SC, KP1, KP2, P1, VAL, IP1);
    cudaEventRecord(evF, 0);
    cudaStreamWaitEvent(sA, evF, 0);
    {
        dim3 g(KP2 / 128, KP2 / 128);
        bf16gemm_xxt<<<g, 256, 0, sA>>>(A1B, G, KP2, KP1, P1);
        pool_A_tri<<<(KP2 * KP2 + 255) / 256, 256, 0, sA>>>(G, A1B, KP1, P1, A2, KP2);
        rowsum_dinv<<<KP2, 256, 0, sA>>>(A2, D2, KP2);
    }
    cudaEventRecord(evA, sA);
    {
        dim3 gw(HP / 128, KP2 / 128, 1);
        bf16g<1, 0, 0, 1><<<gw, 256, SMEM_BF>>>(X1, WP_w2, T0, KP2, HP, HP, HP, HP, HP,
                                                nullptr, P1, VAL);
    }
    cudaStreamWaitEvent(0, evA, 0);
    {
        dim3 g2(HP / 128, KP2 / 128, 6);
        bf16g<1, 0, 1, 0><<<g2, 256, SMEM_BF>>>(A2, T0, PART, KP2, HP, KP2, KP2, HP, HP,
                                                D2, nullptr, nullptr);
        gcn_finish_score<<<(KP2 + 7) / 8, 256>>>(PART, T0, D2, b2, p3, X2, SC, KP2, 6);
    }

    // ==== pool 3 (1536 -> 768) ====
    topk_kernel<2048><<<1, 1024>>>(SC, KP2, KP3, P2, VAL, IP2);
    cudaEventRecord(evF, 0);
    cudaStreamWaitEvent(sA, evF, 0);
    {
        size_t tot = (size_t)KP3 * (KP2 / 4);
        rowgather_f32<<<(unsigned)((tot + 255) / 256), 256, 0, sA>>>(A2, KP2, P2, PART, KP3);
        dim3 g(KP3 / 128, KP3 / 128, 1);
        bf16g<1, 1, 0, 0><<<g, 256, SMEM_BF, sA>>>(PART, PART, G, KP3, KP3, KP2, KP2, KP2, KP3,
                                                   nullptr, nullptr, nullptr);
        pool_A_tri_f32<<<(KP3 * KP3 + 255) / 256, 256, 0, sA>>>(G, PART, KP2, P2, A3, KP3);
        rowsum_dinv<<<KP3, 256, 0, sA>>>(A3, D3, KP3);
    }
    cudaEventRecord(evA, sA);
    {
        dim3 gw(HP / 128, KP3 / 128, 1);
        bf16g<1, 0, 0, 1><<<gw, 256, SMEM_BF>>>(X2, WP_w3, T0, KP3, HP, HP, HP, HP, HP,
                                                nullptr, P2, VAL);
    }
    cudaStreamWaitEvent(0, evA, 0);
    {
        dim3 g2(HP / 128, KP3 / 128, 12);
        bf16g<1, 0, 1, 0><<<g2, 256, SMEM_BF>>>(A3, T0, PART, KP3, HP, KP3, KP3, HP, HP,
                                                D3, nullptr, nullptr);
        gcn_finish_sk<<<(KP3 * HP + 255) / 256, 256>>>(PART, T0, D3, b3, X3, KP3, 1, 12);
    }

    // ==== up 0 ====
    fuse_up<<<(KP2 * HP + 255) / 256, 256>>>(X2, X3, IP2, CUR, KP2);
    {
        dim3 gw(HP / 128, KP2 / 128, 1);
        bf16g<1, 0, 0, 0><<<gw, 256, SMEM_BF>>>(CUR, WP_u0w, T0, KP2, HP, HP, HP, HP, HP,
                                                nullptr, nullptr, nullptr);
        dim3 g2(HP / 128, KP2 / 128, 6);
        bf16g<1, 0, 1, 0><<<g2, 256, SMEM_BF>>>(A2, T0, PART, KP2, HP, KP2, KP2, HP, HP,
                                                D2, nullptr, nullptr);
        gcn_finish_sk<<<(KP2 * HP + 255) / 256, 256>>>(PART, T0, D2, u0b, X2, KP2, 1, 6);
    }

    // ==== up 1 ====
    fuse_up<<<(KP1 * HP + 255) / 256, 256>>>(X1, X2, IP1, CUR, KP1);
    {
        dim3 gw(HP / 128, KP1 / 128, 1);
        bf16g<1, 0, 0, 0><<<gw, 256, SMEM_BF>>>(CUR, WP_u1w, T0, KP1, HP, HP, HP, HP, HP,
                                                nullptr, nullptr, nullptr);
        dim3 g2(HP / 128, KP1 / 128, 6);
        bf16gA<<<g2, 256, SMEM_BA>>>(A1B, T0, PART, KP1, HP, KP1, KP1, HP, HP, D1);
        gcn_finish_sk<<<(KP1 * HP + 255) / 256, 256>>>(PART, T0, D1, u1b, X1, KP1, 1, 6);
    }

    // ==== up 2: final gcn (H->2) + log_softmax ====
    fuse_up<<<(N0 * HP + 255) / 256, 256>>>(X0, X1, IP0, CUR, N0);
    {
        dim3 gf(1, (N0 + 63) / 64);
        gemm64<<<gf, 256>>>(CUR, u2w, T0, N0, 2, H, HP, 2, 2, 2);
        gemm_n2_bf<<<N0, 256>>>(ADJB, T0, D0, CUR, N0);     // AZ into CUR (free)
        final_kernel2<<<(N0 + 255) / 256, 256>>>(CUR, T0, D0, u2b, (float*)d_out, N0);
    }
}